// round 2
// baseline (speedup 1.0000x reference)
#include <cuda_runtime.h>

// Problem constants
#define BATCH 2
#define SEQ   2048
#define CDIM  1024
#define NH    16
#define HD    64
#define MROWS (BATCH * SEQ)      // 4096
#define F3    (3 * CDIM)         // 3072
#define ATTN_SCALE 0.125f        // 64^-0.5
#define NBH   (BATCH * NH)       // 32

// Scratch (static __device__ arrays — allocation-free per harness rules)
__device__ float g_qkv[(size_t)MROWS * F3];            // 50.3 MB  [m, 3*1024]
__device__ float g_S[(size_t)NBH * SEQ * SEQ];         // 536 MB   [z, q, k]
__device__ float g_attn[(size_t)MROWS * CDIM];         // 16.8 MB  [b, n, h*d]

// ---------------------------------------------------------------------------
// NT GEMM body: C[m,n] = sum_k A[m*lda+k] * B[n*ldb+k]  (+ bias[n])
// BM=BN=128, BK=16, 256 threads, 8x8 microtile (split columns for
// conflict-free LDS.128), register-prefetch software pipeline.
// Requires: M,N multiples of 128; K multiple of 16; all pointers 16B-aligned.
// ---------------------------------------------------------------------------
__device__ __forceinline__ void gemm_nt_body(
    const float* __restrict__ A, int lda,
    const float* __restrict__ B, int ldb,
    float* __restrict__ C, int ldc,
    int K, const float* __restrict__ bias,
    int bm, int bn)
{
    __shared__ __align__(16) float As[16][128];
    __shared__ __align__(16) float Bs[16][128];

    const int tid = threadIdx.x;
    const int tx  = tid & 15;
    const int ty  = tid >> 4;
    const int lr  = tid >> 2;        // 0..63
    const int lk  = (tid & 3) * 4;   // 0,4,8,12

    const float* Ab = A + (size_t)bm * lda;
    const float* Bb = B + (size_t)bn * ldb;

    float4 pa0, pa1, pb0, pb1;

    // prologue: tile 0
    pa0 = *(const float4*)(Ab + (size_t)lr        * lda + lk);
    pa1 = *(const float4*)(Ab + (size_t)(lr + 64) * lda + lk);
    pb0 = *(const float4*)(Bb + (size_t)lr        * ldb + lk);
    pb1 = *(const float4*)(Bb + (size_t)(lr + 64) * ldb + lk);

    As[lk+0][lr] = pa0.x; As[lk+1][lr] = pa0.y; As[lk+2][lr] = pa0.z; As[lk+3][lr] = pa0.w;
    As[lk+0][lr+64] = pa1.x; As[lk+1][lr+64] = pa1.y; As[lk+2][lr+64] = pa1.z; As[lk+3][lr+64] = pa1.w;
    Bs[lk+0][lr] = pb0.x; Bs[lk+1][lr] = pb0.y; Bs[lk+2][lr] = pb0.z; Bs[lk+3][lr] = pb0.w;
    Bs[lk+0][lr+64] = pb1.x; Bs[lk+1][lr+64] = pb1.y; Bs[lk+2][lr+64] = pb1.z; Bs[lk+3][lr+64] = pb1.w;
    __syncthreads();

    float acc[8][8];
#pragma unroll
    for (int i = 0; i < 8; ++i)
#pragma unroll
        for (int j = 0; j < 8; ++j) acc[i][j] = 0.0f;

    const int ntiles = K >> 4;
    for (int t = 0; t < ntiles; ++t) {
        if (t + 1 < ntiles) {
            const int k0 = (t + 1) << 4;
            pa0 = *(const float4*)(Ab + (size_t)lr        * lda + k0 + lk);
            pa1 = *(const float4*)(Ab + (size_t)(lr + 64) * lda + k0 + lk);
            pb0 = *(const float4*)(Bb + (size_t)lr        * ldb + k0 + lk);
            pb1 = *(const float4*)(Bb + (size_t)(lr + 64) * ldb + k0 + lk);
        }
#pragma unroll
        for (int k = 0; k < 16; ++k) {
            float4 a0 = *(const float4*)(&As[k][ty * 4]);
            float4 a1 = *(const float4*)(&As[k][ty * 4 + 64]);
            float4 b0 = *(const float4*)(&Bs[k][tx * 4]);
            float4 b1 = *(const float4*)(&Bs[k][tx * 4 + 64]);
            float av[8] = {a0.x, a0.y, a0.z, a0.w, a1.x, a1.y, a1.z, a1.w};
            float bv[8] = {b0.x, b0.y, b0.z, b0.w, b1.x, b1.y, b1.z, b1.w};
#pragma unroll
            for (int i = 0; i < 8; ++i)
#pragma unroll
                for (int j = 0; j < 8; ++j)
                    acc[i][j] = fmaf(av[i], bv[j], acc[i][j]);
        }
        __syncthreads();
        if (t + 1 < ntiles) {
            As[lk+0][lr] = pa0.x; As[lk+1][lr] = pa0.y; As[lk+2][lr] = pa0.z; As[lk+3][lr] = pa0.w;
            As[lk+0][lr+64] = pa1.x; As[lk+1][lr+64] = pa1.y; As[lk+2][lr+64] = pa1.z; As[lk+3][lr+64] = pa1.w;
            Bs[lk+0][lr] = pb0.x; Bs[lk+1][lr] = pb0.y; Bs[lk+2][lr] = pb0.z; Bs[lk+3][lr] = pb0.w;
            Bs[lk+0][lr+64] = pb1.x; Bs[lk+1][lr+64] = pb1.y; Bs[lk+2][lr+64] = pb1.z; Bs[lk+3][lr+64] = pb1.w;
        }
        __syncthreads();
    }

    // epilogue
    float bv0[4] = {0, 0, 0, 0}, bv1[4] = {0, 0, 0, 0};
    if (bias) {
#pragma unroll
        for (int j = 0; j < 4; ++j) {
            bv0[j] = bias[bn + tx * 4 + j];
            bv1[j] = bias[bn + 64 + tx * 4 + j];
        }
    }
#pragma unroll
    for (int i = 0; i < 8; ++i) {
        const int row = bm + ((i < 4) ? (ty * 4 + i) : (64 + ty * 4 + i - 4));
        float* crow = C + (size_t)row * ldc + bn;
        float4 v0 = make_float4(acc[i][0] + bv0[0], acc[i][1] + bv0[1],
                                acc[i][2] + bv0[2], acc[i][3] + bv0[3]);
        float4 v1 = make_float4(acc[i][4] + bv1[0], acc[i][5] + bv1[1],
                                acc[i][6] + bv1[2], acc[i][7] + bv1[3]);
        *(float4*)(crow + tx * 4)      = v0;
        *(float4*)(crow + 64 + tx * 4) = v1;
    }
}

// 1) QKV projection: g_qkv[4096,3072] = x[4096,1024] @ w_qkv[3072,1024]^T
__global__ void __launch_bounds__(256) qkv_kernel(
    const float* __restrict__ x, const float* __restrict__ w)
{
    gemm_nt_body(x, CDIM, w, CDIM, g_qkv, F3, CDIM, nullptr,
                 blockIdx.y * 128, blockIdx.x * 128);
}

// 2) Scores: S_z[q,k] = Q_z[q,:] . K_z[k,:]   (z = b*16 + h)
__global__ void __launch_bounds__(256) scores_kernel()
{
    const int z = blockIdx.z;
    const int b = z >> 4, h = z & 15;
    const float* Q  = g_qkv + (size_t)b * SEQ * F3 + (size_t)h * HD;       // s=0
    const float* Kp = Q + CDIM;                                            // s=1
    float* S = g_S + (size_t)z * SEQ * SEQ;
    gemm_nt_body(Q, F3, Kp, F3, S, SEQ, HD, nullptr,
                 blockIdx.y * 128, blockIdx.x * 128);
}

// 3) Row softmax with folded scale: S = softmax(SCALE * S), in place
__global__ void __launch_bounds__(256) softmax_kernel()
{
    __shared__ float red[8];
    const size_t row = blockIdx.x;
    float4* p4 = (float4*)(g_S + row * SEQ);
    const int tid = threadIdx.x;
    const int lane = tid & 31, wid = tid >> 5;

    float4 v0 = p4[tid];
    float4 v1 = p4[tid + 256];

    float m = fmaxf(fmaxf(fmaxf(v0.x, v0.y), fmaxf(v0.z, v0.w)),
                    fmaxf(fmaxf(v1.x, v1.y), fmaxf(v1.z, v1.w)));
#pragma unroll
    for (int o = 16; o; o >>= 1) m = fmaxf(m, __shfl_xor_sync(0xffffffffu, m, o));
    if (lane == 0) red[wid] = m;
    __syncthreads();
    if (tid < 32) {
        float t = (lane < 8) ? red[lane] : -3.0e38f;
#pragma unroll
        for (int o = 4; o; o >>= 1) t = fmaxf(t, __shfl_xor_sync(0xffffffffu, t, o));
        if (lane == 0) red[0] = t;
    }
    __syncthreads();
    const float M = red[0];
    __syncthreads();

    v0.x = __expf((v0.x - M) * ATTN_SCALE);
    v0.y = __expf((v0.y - M) * ATTN_SCALE);
    v0.z = __expf((v0.z - M) * ATTN_SCALE);
    v0.w = __expf((v0.w - M) * ATTN_SCALE);
    v1.x = __expf((v1.x - M) * ATTN_SCALE);
    v1.y = __expf((v1.y - M) * ATTN_SCALE);
    v1.z = __expf((v1.z - M) * ATTN_SCALE);
    v1.w = __expf((v1.w - M) * ATTN_SCALE);

    float s = v0.x + v0.y + v0.z + v0.w + v1.x + v1.y + v1.z + v1.w;
#pragma unroll
    for (int o = 16; o; o >>= 1) s += __shfl_xor_sync(0xffffffffu, s, o);
    if (lane == 0) red[wid] = s;
    __syncthreads();
    if (tid < 32) {
        float t = (lane < 8) ? red[lane] : 0.0f;
#pragma unroll
        for (int o = 4; o; o >>= 1) t += __shfl_xor_sync(0xffffffffu, t, o);
        if (lane == 0) red[0] = t;
    }
    __syncthreads();
    const float r = 1.0f / red[0];

    v0.x *= r; v0.y *= r; v0.z *= r; v0.w *= r;
    v1.x *= r; v1.y *= r; v1.z *= r; v1.w *= r;
    p4[tid]       = v0;
    p4[tid + 256] = v1;
}

// 4) PV (NN GEMM): attn[b,q,h*64+d] = sum_k P_z[q,k] * V_z[k,d]
//    BM=128, BN=64, BK=16, 256 threads, 8x4 microtile.
__global__ void __launch_bounds__(256) pv_kernel()
{
    __shared__ __align__(16) float As[16][128];
    __shared__ __align__(16) float Bs[16][64];

    const int z = blockIdx.z;
    const int b = z >> 4, h = z & 15;
    const float* A  = g_S   + (size_t)z * SEQ * SEQ;
    const float* Bv = g_qkv + (size_t)b * SEQ * F3 + 2 * CDIM + (size_t)h * HD; // s=2
    float* C        = g_attn + (size_t)b * SEQ * CDIM + (size_t)h * HD;

    const int tid = threadIdx.x;
    const int tx  = tid & 15;
    const int ty  = tid >> 4;
    const int lr  = tid >> 2;        // A loader row 0..63
    const int lk  = (tid & 3) * 4;   // A loader k 0,4,8,12
    const int br  = tid >> 4;        // B loader k-row 0..15
    const int bc  = (tid & 15) * 4;  // B loader col 0..60

    const int bm = blockIdx.y * 128;
    const float* Ab = A + (size_t)bm * SEQ;

    float4 pa0, pa1, pb;
    pa0 = *(const float4*)(Ab + (size_t)lr        * SEQ + lk);
    pa1 = *(const float4*)(Ab + (size_t)(lr + 64) * SEQ + lk);
    pb  = *(const float4*)(Bv + (size_t)br * F3 + bc);

    As[lk+0][lr] = pa0.x; As[lk+1][lr] = pa0.y; As[lk+2][lr] = pa0.z; As[lk+3][lr] = pa0.w;
    As[lk+0][lr+64] = pa1.x; As[lk+1][lr+64] = pa1.y; As[lk+2][lr+64] = pa1.z; As[lk+3][lr+64] = pa1.w;
    *(float4*)(&Bs[br][bc]) = pb;
    __syncthreads();

    float acc[8][4];
#pragma unroll
    for (int i = 0; i < 8; ++i)
#pragma unroll
        for (int j = 0; j < 4; ++j) acc[i][j] = 0.0f;

    const int ntiles = SEQ >> 4;  // 128
    for (int t = 0; t < ntiles; ++t) {
        if (t + 1 < ntiles) {
            const int k0 = (t + 1) << 4;
            pa0 = *(const float4*)(Ab + (size_t)lr        * SEQ + k0 + lk);
            pa1 = *(const float4*)(Ab + (size_t)(lr + 64) * SEQ + k0 + lk);
            pb  = *(const float4*)(Bv + (size_t)(k0 + br) * F3 + bc);
        }
#pragma unroll
        for (int k = 0; k < 16; ++k) {
            float4 a0 = *(const float4*)(&As[k][ty * 4]);
            float4 a1 = *(const float4*)(&As[k][ty * 4 + 64]);
            float4 b4 = *(const float4*)(&Bs[k][tx * 4]);
            float av[8] = {a0.x, a0.y, a0.z, a0.w, a1.x, a1.y, a1.z, a1.w};
            float bv[4] = {b4.x, b4.y, b4.z, b4.w};
#pragma unroll
            for (int i = 0; i < 8; ++i)
#pragma unroll
                for (int j = 0; j < 4; ++j)
                    acc[i][j] = fmaf(av[i], bv[j], acc[i][j]);
        }
        __syncthreads();
        if (t + 1 < ntiles) {
            As[lk+0][lr] = pa0.x; As[lk+1][lr] = pa0.y; As[lk+2][lr] = pa0.z; As[lk+3][lr] = pa0.w;
            As[lk+0][lr+64] = pa1.x; As[lk+1][lr+64] = pa1.y; As[lk+2][lr+64] = pa1.z; As[lk+3][lr+64] = pa1.w;
            *(float4*)(&Bs[br][bc]) = pb;
        }
        __syncthreads();
    }

#pragma unroll
    for (int i = 0; i < 8; ++i) {
        const int row = bm + ((i < 4) ? (ty * 4 + i) : (64 + ty * 4 + i - 4));
        float4 v = make_float4(acc[i][0], acc[i][1], acc[i][2], acc[i][3]);
        *(float4*)(C + (size_t)row * CDIM + tx * 4) = v;
    }
}

// 5) Output projection: out[4096,1024] = attn[4096,1024] @ w_out[1024,1024]^T + b
__global__ void __launch_bounds__(256) proj_kernel(
    const float* __restrict__ w, const float* __restrict__ bias,
    float* __restrict__ out)
{
    gemm_nt_body(g_attn, CDIM, w, CDIM, out, CDIM, CDIM, bias,
                 blockIdx.y * 128, blockIdx.x * 128);
}

extern "C" void kernel_launch(void* const* d_in, const int* in_sizes, int n_in,
                              void* d_out, int out_size)
{
    (void)in_sizes; (void)n_in; (void)out_size;
    const float* x     = (const float*)d_in[0];
    const float* w_qkv = (const float*)d_in[1];
    const float* w_out = (const float*)d_in[2];
    const float* b_out = (const float*)d_in[3];
    float* out = (float*)d_out;

    qkv_kernel<<<dim3(F3 / 128, MROWS / 128), 256>>>(x, w_qkv);
    scores_kernel<<<dim3(SEQ / 128, SEQ / 128, NBH), 256>>>();
    softmax_kernel<<<dim3(NBH * SEQ), 256>>>();
    pv_kernel<<<dim3(1, SEQ / 128, NBH), 256>>>();
    proj_kernel<<<dim3(CDIM / 128, MROWS / 128), 256>>>(w_out, b_out, out);
}

// round 8
// speedup vs baseline: 1.6799x; 1.6799x over previous
#include <cuda_runtime.h>
#include <cuda_bf16.h>
#include <cstdint>

#define BATCH 2
#define SEQ   2048
#define CDIM  1024
#define NH    16
#define HD    64
#define MROWS (BATCH * SEQ)      // 4096
#define F3    (3 * CDIM)         // 3072
#define ATTN_SCALE 0.125f
#define NBH   (BATCH * NH)       // 32

// ---------------------------------------------------------------------------
// Static scratch (allocation-free)
// ---------------------------------------------------------------------------
__device__ __nv_bfloat16 g_x_hi[(size_t)MROWS * CDIM];
__device__ __nv_bfloat16 g_x_lo[(size_t)MROWS * CDIM];
__device__ __nv_bfloat16 g_wqkv_hi[(size_t)F3 * CDIM];
__device__ __nv_bfloat16 g_wqkv_lo[(size_t)F3 * CDIM];
__device__ __nv_bfloat16 g_wout_hi[(size_t)CDIM * CDIM];
__device__ __nv_bfloat16 g_wout_lo[(size_t)CDIM * CDIM];
__device__ __nv_bfloat16 g_qkv_hi[(size_t)MROWS * F3];
__device__ __nv_bfloat16 g_qkv_lo[(size_t)MROWS * F3];
__device__ float         g_S[(size_t)NBH * SEQ * SEQ];
__device__ __nv_bfloat16 g_P_hi[(size_t)NBH * SEQ * SEQ];
__device__ __nv_bfloat16 g_P_lo[(size_t)NBH * SEQ * SEQ];
__device__ __nv_bfloat16 g_attn_hi[(size_t)MROWS * CDIM];
__device__ __nv_bfloat16 g_attn_lo[(size_t)MROWS * CDIM];

// ---------------------------------------------------------------------------
// Helpers
// ---------------------------------------------------------------------------
__device__ __forceinline__ uint32_t smem_u32(const void* p) {
    uint32_t a;
    asm("{ .reg .u64 t; cvta.to.shared.u64 t, %1; cvt.u32.u64 %0, t; }"
        : "=r"(a) : "l"(p));
    return a;
}
__device__ __forceinline__ void cvt_hilo(float x, __nv_bfloat16& h, __nv_bfloat16& l) {
    h = __float2bfloat16(x);
    l = __float2bfloat16(x - __bfloat162float(h));
}
__device__ __forceinline__ uint32_t pk(__nv_bfloat16 a, __nv_bfloat16 b) {
    return (uint32_t)__bfloat16_as_ushort(a) | ((uint32_t)__bfloat16_as_ushort(b) << 16);
}

#define LDMX4(r0, r1, r2, r3, addr)                                            \
    asm volatile("ldmatrix.sync.aligned.m8n8.x4.shared.b16 {%0,%1,%2,%3}, [%4];" \
                 : "=r"(r0), "=r"(r1), "=r"(r2), "=r"(r3) : "r"(addr))

__device__ __forceinline__ void mma16816(float* c, uint32_t a0, uint32_t a1,
                                         uint32_t a2, uint32_t a3,
                                         uint32_t b0, uint32_t b1) {
    asm volatile(
        "mma.sync.aligned.m16n8k16.row.col.f32.bf16.bf16.f32 "
        "{%0,%1,%2,%3}, {%4,%5,%6,%7}, {%8,%9}, {%0,%1,%2,%3};"
        : "+f"(c[0]), "+f"(c[1]), "+f"(c[2]), "+f"(c[3])
        : "r"(a0), "r"(a1), "r"(a2), "r"(a3), "r"(b0), "r"(b1));
}

#define CP16(dst, src) \
    asm volatile("cp.async.cg.shared.global [%0], [%1], 16;" :: "r"(dst), "l"(src))
#define CP_COMMIT() asm volatile("cp.async.commit_group;" ::: "memory")
#define CP_WAIT1()  asm volatile("cp.async.wait_group 1;" ::: "memory")
#define CP_WAIT0()  asm volatile("cp.async.wait_group 0;" ::: "memory")

// Smem tile geometry: bf16 tiles, 32 k-elems per row + pad -> 80B row stride
#define LDS_B   80
#define A_TILE  10240            // 128 rows * 80B
#define B_TILE128 10240
#define B_TILE64  5120
// generic buffer: AHI, ALO, BHI, BLO (128-row B)
#define G_BUFSZ (2 * A_TILE + 2 * B_TILE128)   // 40960
// pv buffer: AHI, ALO, BHI(64), BLO(64)
#define P_BUFSZ (2 * A_TILE + 2 * B_TILE64)    // 30720

// cp.async a 128x32 bf16 hi+lo tile pair into padded smem
__device__ __forceinline__ void cp_tile128(
    uint32_t sm_hi, uint32_t sm_lo,
    const __nv_bfloat16* __restrict__ ghi, const __nv_bfloat16* __restrict__ glo,
    int ld, int tid)
{
#pragma unroll
    for (int it = 0; it < 4; ++it) {
        int idx = tid + 256 * it;            // 0..1023 16B chunks
        int mat = idx >> 9;                  // 0 = hi, 1 = lo
        int r   = (idx >> 2) & 127;
        int c   = idx & 3;
        uint32_t dst = (mat ? sm_lo : sm_hi) + (uint32_t)(r * LDS_B + c * 16);
        const __nv_bfloat16* src = (mat ? glo : ghi) + (size_t)r * ld + c * 8;
        CP16(dst, src);
    }
}

// 3-pass (hh + hl + lh) bf16 MMA over one 32-deep k-tile
template <int NF>
__device__ __forceinline__ void compute_ktile(
    uint32_t aHi, uint32_t aLo, uint32_t bHi, uint32_t bLo,
    int m0, int n0, int lane, float (&acc)[4][NF][4])
{
#pragma unroll
    for (int ks = 0; ks < 2; ++ks) {
        const uint32_t acol = (uint32_t)(ks * 32 + (lane >> 4) * 16);
        const uint32_t bcol = (uint32_t)(ks * 32 + ((lane >> 3) & 1) * 16);
        const int arow = m0 + (lane & 15);
        const int brow = n0 + 8 * (lane >> 4) + (lane & 7);

        uint32_t ah[4][4], bh[NF][2], bl[NF][2];
#pragma unroll
        for (int i = 0; i < 4; ++i) {
            uint32_t ad = aHi + (uint32_t)((arow + 16 * i) * LDS_B) + acol;
            LDMX4(ah[i][0], ah[i][1], ah[i][2], ah[i][3], ad);
        }
#pragma unroll
        for (int j = 0; j < NF; j += 2) {
            uint32_t off = (uint32_t)((brow + 8 * j) * LDS_B) + bcol;
            LDMX4(bh[j][0], bh[j][1], bh[j + 1][0], bh[j + 1][1], bHi + off);
            LDMX4(bl[j][0], bl[j][1], bl[j + 1][0], bl[j + 1][1], bLo + off);
        }
#pragma unroll
        for (int i = 0; i < 4; ++i)
#pragma unroll
            for (int j = 0; j < NF; ++j) {
                mma16816(acc[i][j], ah[i][0], ah[i][1], ah[i][2], ah[i][3],
                         bh[j][0], bh[j][1]);
                mma16816(acc[i][j], ah[i][0], ah[i][1], ah[i][2], ah[i][3],
                         bl[j][0], bl[j][1]);
            }
#pragma unroll
        for (int i = 0; i < 4; ++i) {
            uint32_t al[4];
            uint32_t ad = aLo + (uint32_t)((arow + 16 * i) * LDS_B) + acol;
            LDMX4(al[0], al[1], al[2], al[3], ad);
#pragma unroll
            for (int j = 0; j < NF; ++j)
                mma16816(acc[i][j], al[0], al[1], al[2], al[3],
                         bh[j][0], bh[j][1]);
        }
    }
}

// ---------------------------------------------------------------------------
// Generic NT GEMM (tile 128x128, k-tiles of 32):
//  mode 0: qkv    A=x(hi/lo) [4096,1024]  B=w_qkv(hi/lo)  -> g_qkv hi/lo (bf16)
//  mode 1: scores A=Q_z      B=K_z (K=64) -> g_S (fp32)
//  mode 2: proj   A=attn     B=w_out      -> out fp32 (+bias)
// ---------------------------------------------------------------------------
__global__ void __launch_bounds__(256) mma_gemm(int mode,
                                                const float* __restrict__ bias,
                                                float* __restrict__ outp)
{
    extern __shared__ char smem[];
    const int tid  = threadIdx.x;
    const int wid  = tid >> 5, lane = tid & 31;
    const int m0   = (wid >> 2) * 64;
    const int n0   = (wid & 3) * 32;
    const uint32_t sb = smem_u32(smem);

    const int bm = blockIdx.y * 128, bn = blockIdx.x * 128;
    const int z  = blockIdx.z;

    const __nv_bfloat16 *ahi, *alo, *bhi, *blo;
    int lda, ldb, K;
    if (mode == 0) {
        ahi = g_x_hi + (size_t)bm * CDIM;  alo = g_x_lo + (size_t)bm * CDIM;
        bhi = g_wqkv_hi + (size_t)bn * CDIM; blo = g_wqkv_lo + (size_t)bn * CDIM;
        lda = CDIM; ldb = CDIM; K = CDIM;
    } else if (mode == 1) {
        const int b = z >> 4, h = z & 15;
        size_t ao = (size_t)(b * SEQ + bm) * F3 + (size_t)h * HD;
        size_t bo = (size_t)(b * SEQ + bn) * F3 + CDIM + (size_t)h * HD;
        ahi = g_qkv_hi + ao; alo = g_qkv_lo + ao;
        bhi = g_qkv_hi + bo; blo = g_qkv_lo + bo;
        lda = F3; ldb = F3; K = HD;
    } else {
        ahi = g_attn_hi + (size_t)bm * CDIM; alo = g_attn_lo + (size_t)bm * CDIM;
        bhi = g_wout_hi + (size_t)bn * CDIM; blo = g_wout_lo + (size_t)bn * CDIM;
        lda = CDIM; ldb = CDIM; K = CDIM;
    }

    const uint32_t sAhi[2] = {sb,            sb + G_BUFSZ};
    const uint32_t sAlo[2] = {sb + A_TILE,   sb + G_BUFSZ + A_TILE};
    const uint32_t sBhi[2] = {sb + 2*A_TILE, sb + G_BUFSZ + 2*A_TILE};
    const uint32_t sBlo[2] = {sb + 2*A_TILE + B_TILE128,
                              sb + G_BUFSZ + 2*A_TILE + B_TILE128};

    float acc[4][4][4];
#pragma unroll
    for (int i = 0; i < 4; ++i)
#pragma unroll
        for (int j = 0; j < 4; ++j)
#pragma unroll
            for (int k = 0; k < 4; ++k) acc[i][j][k] = 0.0f;

    const int nt = K >> 5;
    // prologue: tile 0
    cp_tile128(sAhi[0], sAlo[0], ahi, alo, lda, tid);
    cp_tile128(sBhi[0], sBlo[0], bhi, blo, ldb, tid);
    CP_COMMIT();

    for (int t = 0; t < nt; ++t) {
        const int bf = t & 1;
        if (t + 1 < nt) {
            const int nb = (t + 1) & 1, k0 = (t + 1) << 5;
            cp_tile128(sAhi[nb], sAlo[nb], ahi + k0, alo + k0, lda, tid);
            cp_tile128(sBhi[nb], sBlo[nb], bhi + k0, blo + k0, ldb, tid);
            CP_COMMIT();
            CP_WAIT1();
        } else {
            CP_WAIT0();
        }
        __syncthreads();
        compute_ktile<4>(sAhi[bf], sAlo[bf], sBhi[bf], sBlo[bf], m0, n0, lane, acc);
        __syncthreads();
    }

    // epilogue
    if (mode == 1 || mode == 2) {
        float* C = (mode == 1) ? (g_S + (size_t)z * SEQ * SEQ) : outp;
        const int ldc = (mode == 1) ? SEQ : CDIM;
#pragma unroll
        for (int i = 0; i < 4; ++i) {
            const int r0 = bm + m0 + 16 * i + (lane >> 2);
#pragma unroll
            for (int j = 0; j < 4; ++j) {
                const int col = bn + n0 + 8 * j + (lane & 3) * 2;
                float b0 = 0.f, b1 = 0.f;
                if (mode == 2 && bias) { b0 = bias[col]; b1 = bias[col + 1]; }
                float2 v0 = make_float2(acc[i][j][0] + b0, acc[i][j][1] + b1);
                float2 v1 = make_float2(acc[i][j][2] + b0, acc[i][j][3] + b1);
                *(float2*)(C + (size_t)r0 * ldc + col) = v0;
                *(float2*)(C + (size_t)(r0 + 8) * ldc + col) = v1;
            }
        }
    } else {  // qkv -> bf16 hi/lo
#pragma unroll
        for (int i = 0; i < 4; ++i) {
            const int r0 = bm + m0 + 16 * i + (lane >> 2);
#pragma unroll
            for (int j = 0; j < 4; ++j) {
                const int col = bn + n0 + 8 * j + (lane & 3) * 2;
                __nv_bfloat16 h0, h1, l0, l1;
#pragma unroll
                for (int half = 0; half < 2; ++half) {
                    cvt_hilo(acc[i][j][2 * half + 0], h0, l0);
                    cvt_hilo(acc[i][j][2 * half + 1], h1, l1);
                    const size_t off = (size_t)(r0 + 8 * half) * F3 + col;
                    *(uint32_t*)(g_qkv_hi + off) = pk(h0, h1);
                    *(uint32_t*)(g_qkv_lo + off) = pk(l0, l1);
                }
            }
        }
    }
}

// ---------------------------------------------------------------------------
// PV: attn[128q x 64d] = P[128q x 2048k] @ V[2048k x 64d]  (tile 128x64x32)
// ---------------------------------------------------------------------------
__global__ void __launch_bounds__(256) pv_mma()
{
    extern __shared__ char smem[];
    const int tid  = threadIdx.x;
    const int wid  = tid >> 5, lane = tid & 31;
    const int m0   = (wid >> 2) * 64;
    const int n0   = (wid & 3) * 16;
    const uint32_t sb = smem_u32(smem);

    const int z = blockIdx.y, b = z >> 4, h = z & 15;
    const int bm = blockIdx.x * 128;
    const __nv_bfloat16* phi = g_P_hi + (size_t)z * SEQ * SEQ + (size_t)bm * SEQ;
    const __nv_bfloat16* plo = g_P_lo + (size_t)z * SEQ * SEQ + (size_t)bm * SEQ;
    const size_t voff = (size_t)b * SEQ * F3 + 2 * CDIM + (size_t)h * HD;
    const __nv_bfloat16* vhi = g_qkv_hi + voff;
    const __nv_bfloat16* vlo = g_qkv_lo + voff;

    const uint32_t sAhi[2] = {sb,            sb + P_BUFSZ};
    const uint32_t sAlo[2] = {sb + A_TILE,   sb + P_BUFSZ + A_TILE};
    const uint32_t sBhi[2] = {sb + 2*A_TILE, sb + P_BUFSZ + 2*A_TILE};
    const uint32_t sBlo[2] = {sb + 2*A_TILE + B_TILE64,
                              sb + P_BUFSZ + 2*A_TILE + B_TILE64};

    // V^T loader: 32 k-rows x 64 d -> Bs[d][kk]
    auto load_vT = [&](int buf, int k0) {
        char* bh = smem + (buf ? P_BUFSZ : 0) + 2 * A_TILE;
        char* bl = bh + B_TILE64;
#pragma unroll
        for (int it = 0; it < 2; ++it) {
            int idx = tid + 256 * it;          // 0..511 uint2 units
            int kk = idx >> 4, dg = idx & 15;
            uint2 vh = *(const uint2*)(vhi + (size_t)(k0 + kk) * F3 + dg * 4);
            uint2 vl = *(const uint2*)(vlo + (size_t)(k0 + kk) * F3 + dg * 4);
            unsigned short hs[4] = {(unsigned short)vh.x, (unsigned short)(vh.x >> 16),
                                    (unsigned short)vh.y, (unsigned short)(vh.y >> 16)};
            unsigned short ls[4] = {(unsigned short)vl.x, (unsigned short)(vl.x >> 16),
                                    (unsigned short)vl.y, (unsigned short)(vl.y >> 16)};
#pragma unroll
            for (int j = 0; j < 4; ++j) {
                int off = (dg * 4 + j) * LDS_B + kk * 2;
                *(unsigned short*)(bh + off) = hs[j];
                *(unsigned short*)(bl + off) = ls[j];
            }
        }
    };

    float acc[4][2][4];
#pragma unroll
    for (int i = 0; i < 4; ++i)
#pragma unroll
        for (int j = 0; j < 2; ++j)
#pragma unroll
            for (int k = 0; k < 4; ++k) acc[i][j][k] = 0.0f;

    const int nt = SEQ >> 5;   // 64
    cp_tile128(sAhi[0], sAlo[0], phi, plo, SEQ, tid);
    CP_COMMIT();
    load_vT(0, 0);

    for (int t = 0; t < nt; ++t) {
        const int bf = t & 1;
        if (t + 1 < nt) {
            const int nb = (t + 1) & 1, k0 = (t + 1) << 5;
            cp_tile128(sAhi[nb], sAlo[nb], phi + k0, plo + k0, SEQ, tid);
            CP_COMMIT();
            load_vT(nb, k0);
            CP_WAIT1();
        } else {
            CP_WAIT0();
        }
        __syncthreads();
        compute_ktile<2>(sAhi[bf], sAlo[bf], sBhi[bf], sBlo[bf], m0, n0, lane, acc);
        __syncthreads();
    }

    // epilogue -> attn hi/lo bf16
    const int rowbase = b * SEQ + bm;
#pragma unroll
    for (int i = 0; i < 4; ++i) {
        const int r0 = rowbase + m0 + 16 * i + (lane >> 2);
#pragma unroll
        for (int j = 0; j < 2; ++j) {
            const int col = h * HD + n0 + 8 * j + (lane & 3) * 2;
            __nv_bfloat16 h0, h1, l0, l1;
#pragma unroll
            for (int half = 0; half < 2; ++half) {
                cvt_hilo(acc[i][j][2 * half + 0], h0, l0);
                cvt_hilo(acc[i][j][2 * half + 1], h1, l1);
                const size_t off = (size_t)(r0 + 8 * half) * CDIM + col;
                *(uint32_t*)(g_attn_hi + off) = pk(h0, h1);
                *(uint32_t*)(g_attn_lo + off) = pk(l0, l1);
            }
        }
    }
}

// ---------------------------------------------------------------------------
// fp32 -> bf16 hi/lo elementwise convert
// ---------------------------------------------------------------------------
__global__ void __launch_bounds__(256) cvt_kernel(
    const float4* __restrict__ src, uint2* __restrict__ hi,
    uint2* __restrict__ lo, int n4)
{
    int i = blockIdx.x * blockDim.x + threadIdx.x;
    if (i >= n4) return;
    float4 v = src[i];
    __nv_bfloat16 h0, h1, h2, h3, l0, l1, l2, l3;
    cvt_hilo(v.x, h0, l0); cvt_hilo(v.y, h1, l1);
    cvt_hilo(v.z, h2, l2); cvt_hilo(v.w, h3, l3);
    hi[i] = make_uint2(pk(h0, h1), pk(h2, h3));
    lo[i] = make_uint2(pk(l0, l1), pk(l2, l3));
}

// ---------------------------------------------------------------------------
// Softmax (folded scale): P = softmax(SCALE*S), written as bf16 hi/lo
// ---------------------------------------------------------------------------
__global__ void __launch_bounds__(256) softmax_kernel()
{
    __shared__ float red[8];
    const size_t row = blockIdx.x;
    const float4* p4 = (const float4*)(g_S + row * SEQ);
    const int tid = threadIdx.x;
    const int lane = tid & 31, wid = tid >> 5;

    float4 v0 = p4[tid];
    float4 v1 = p4[tid + 256];

    float m = fmaxf(fmaxf(fmaxf(v0.x, v0.y), fmaxf(v0.z, v0.w)),
                    fmaxf(fmaxf(v1.x, v1.y), fmaxf(v1.z, v1.w)));
#pragma unroll
    for (int o = 16; o; o >>= 1) m = fmaxf(m, __shfl_xor_sync(0xffffffffu, m, o));
    if (lane == 0) red[wid] = m;
    __syncthreads();
    if (tid < 32) {
        float t = (lane < 8) ? red[lane] : -3.0e38f;
#pragma unroll
        for (int o = 4; o; o >>= 1) t = fmaxf(t, __shfl_xor_sync(0xffffffffu, t, o));
        if (lane == 0) red[0] = t;
    }
    __syncthreads();
    const float M = red[0];
    __syncthreads();

    v0.x = __expf((v0.x - M) * ATTN_SCALE);
    v0.y = __expf((v0.y - M) * ATTN_SCALE);
    v0.z = __expf((v0.z - M) * ATTN_SCALE);
    v0.w = __expf((v0.w - M) * ATTN_SCALE);
    v1.x = __expf((v1.x - M) * ATTN_SCALE);
    v1.y = __expf((v1.y - M) * ATTN_SCALE);
    v1.z = __expf((v1.z - M) * ATTN_SCALE);
    v1.w = __expf((v1.w - M) * ATTN_SCALE);

    float s = v0.x + v0.y + v0.z + v0.w + v1.x + v1.y + v1.z + v1.w;
#pragma unroll
    for (int o = 16; o; o >>= 1) s += __shfl_xor_sync(0xffffffffu, s, o);
    if (lane == 0) red[wid] = s;
    __syncthreads();
    if (tid < 32) {
        float t = (lane < 8) ? red[lane] : 0.0f;
#pragma unroll
        for (int o = 4; o; o >>= 1) t += __shfl_xor_sync(0xffffffffu, t, o);
        if (lane == 0) red[0] = t;
    }
    __syncthreads();
    const float r = 1.0f / red[0];

    float vals[8] = {v0.x * r, v0.y * r, v0.z * r, v0.w * r,
                     v1.x * r, v1.y * r, v1.z * r, v1.w * r};
    __nv_bfloat16 hh[8], ll[8];
#pragma unroll
    for (int j = 0; j < 8; ++j) cvt_hilo(vals[j], hh[j], ll[j]);

    uint2* ph = (uint2*)(g_P_hi + row * SEQ);
    uint2* pl = (uint2*)(g_P_lo + row * SEQ);
    ph[tid]       = make_uint2(pk(hh[0], hh[1]), pk(hh[2], hh[3]));
    ph[tid + 256] = make_uint2(pk(hh[4], hh[5]), pk(hh[6], hh[7]));
    pl[tid]       = make_uint2(pk(ll[0], ll[1]), pk(ll[2], ll[3]));
    pl[tid + 256] = make_uint2(pk(ll[4], ll[5]), pk(ll[6], ll[7]));
}

// ---------------------------------------------------------------------------
extern "C" void kernel_launch(void* const* d_in, const int* in_sizes, int n_in,
                              void* d_out, int out_size)
{
    (void)in_sizes; (void)n_in; (void)out_size;
    const float* x     = (const float*)d_in[0];
    const float* w_qkv = (const float*)d_in[1];
    const float* w_out = (const float*)d_in[2];
    const float* b_out = (const float*)d_in[3];
    float* out = (float*)d_out;

    static int attr_done = 0;
    if (!attr_done) {
        cudaFuncSetAttribute(mma_gemm, cudaFuncAttributeMaxDynamicSharedMemorySize,
                             2 * G_BUFSZ);
        cudaFuncSetAttribute(pv_mma, cudaFuncAttributeMaxDynamicSharedMemorySize,
                             2 * P_BUFSZ);
        attr_done = 1;
    }

    __nv_bfloat16 *xh, *xl, *qh, *ql, *oh, *ol;
    cudaGetSymbolAddress((void**)&xh, g_x_hi);
    cudaGetSymbolAddress((void**)&xl, g_x_lo);
    cudaGetSymbolAddress((void**)&qh, g_wqkv_hi);
    cudaGetSymbolAddress((void**)&ql, g_wqkv_lo);
    cudaGetSymbolAddress((void**)&oh, g_wout_hi);
    cudaGetSymbolAddress((void**)&ol, g_wout_lo);

    // input conversions
    {
        int n4 = MROWS * CDIM / 4;
        cvt_kernel<<<(n4 + 255) / 256, 256>>>((const float4*)x, (uint2*)xh, (uint2*)xl, n4);
        n4 = F3 * CDIM / 4;
        cvt_kernel<<<(n4 + 255) / 256, 256>>>((const float4*)w_qkv, (uint2*)qh, (uint2*)ql, n4);
        n4 = CDIM * CDIM / 4;
        cvt_kernel<<<(n4 + 255) / 256, 256>>>((const float4*)w_out, (uint2*)oh, (uint2*)ol, n4);
    }

    // 1) QKV -> g_qkv hi/lo
    mma_gemm<<<dim3(F3 / 128, MROWS / 128, 1), 256, 2 * G_BUFSZ>>>(0, nullptr, nullptr);
    // 2) scores -> g_S
    mma_gemm<<<dim3(SEQ / 128, SEQ / 128, NBH), 256, 2 * G_BUFSZ>>>(1, nullptr, nullptr);
    // 3) softmax -> P hi/lo
    softmax_kernel<<<dim3(NBH * SEQ), 256>>>();
    // 4) PV -> attn hi/lo
    pv_mma<<<dim3(SEQ / 128, NBH), 256, 2 * P_BUFSZ>>>();
    // 5) proj -> out (+bias)
    mma_gemm<<<dim3(CDIM / 128, MROWS / 128, 1), 256, 2 * G_BUFSZ>>>(2, b_out, out);
}

// round 9
// speedup vs baseline: 2.1575x; 1.2843x over previous
#include <cuda_runtime.h>
#include <cuda_bf16.h>
#include <cstdint>

#define BATCH 2
#define SEQ   2048
#define CDIM  1024
#define NH    16
#define HD    64
#define MROWS (BATCH * SEQ)      // 4096
#define F3    (3 * CDIM)         // 3072
#define ATTN_SCALE 0.125f
#define NBH   (BATCH * NH)       // 32

// ---------------------------------------------------------------------------
// Static scratch (allocation-free)
// ---------------------------------------------------------------------------
__device__ __nv_bfloat16 g_x_hi[(size_t)MROWS * CDIM];
__device__ __nv_bfloat16 g_x_lo[(size_t)MROWS * CDIM];
__device__ __nv_bfloat16 g_wqkv_hi[(size_t)F3 * CDIM];
__device__ __nv_bfloat16 g_wqkv_lo[(size_t)F3 * CDIM];
__device__ __nv_bfloat16 g_wout_hi[(size_t)CDIM * CDIM];
__device__ __nv_bfloat16 g_wout_lo[(size_t)CDIM * CDIM];
__device__ __nv_bfloat16 g_qkv_hi[(size_t)MROWS * F3];
__device__ __nv_bfloat16 g_qkv_lo[(size_t)MROWS * F3];
__device__ __nv_bfloat16 g_attn_hi[(size_t)MROWS * CDIM];
__device__ __nv_bfloat16 g_attn_lo[(size_t)MROWS * CDIM];

// ---------------------------------------------------------------------------
// Helpers
// ---------------------------------------------------------------------------
__device__ __forceinline__ uint32_t smem_u32(const void* p) {
    uint32_t a;
    asm("{ .reg .u64 t; cvta.to.shared.u64 t, %1; cvt.u32.u64 %0, t; }"
        : "=r"(a) : "l"(p));
    return a;
}
__device__ __forceinline__ void cvt_hilo(float x, __nv_bfloat16& h, __nv_bfloat16& l) {
    h = __float2bfloat16(x);
    l = __float2bfloat16(x - __bfloat162float(h));
}
__device__ __forceinline__ uint32_t pk(__nv_bfloat16 a, __nv_bfloat16 b) {
    return (uint32_t)__bfloat16_as_ushort(a) | ((uint32_t)__bfloat16_as_ushort(b) << 16);
}

#define LDMX4(r0, r1, r2, r3, addr)                                            \
    asm volatile("ldmatrix.sync.aligned.m8n8.x4.shared.b16 {%0,%1,%2,%3}, [%4];" \
                 : "=r"(r0), "=r"(r1), "=r"(r2), "=r"(r3) : "r"(addr))

__device__ __forceinline__ void mma16816(float* c, uint32_t a0, uint32_t a1,
                                         uint32_t a2, uint32_t a3,
                                         uint32_t b0, uint32_t b1) {
    asm volatile(
        "mma.sync.aligned.m16n8k16.row.col.f32.bf16.bf16.f32 "
        "{%0,%1,%2,%3}, {%4,%5,%6,%7}, {%8,%9}, {%0,%1,%2,%3};"
        : "+f"(c[0]), "+f"(c[1]), "+f"(c[2]), "+f"(c[3])
        : "r"(a0), "r"(a1), "r"(a2), "r"(a3), "r"(b0), "r"(b1));
}

#define CP16(dst, src) \
    asm volatile("cp.async.cg.shared.global [%0], [%1], 16;" :: "r"(dst), "l"(src))
#define CP_COMMIT() asm volatile("cp.async.commit_group;" ::: "memory")
#define CP_WAIT1()  asm volatile("cp.async.wait_group 1;" ::: "memory")
#define CP_WAIT0()  asm volatile("cp.async.wait_group 0;" ::: "memory")

// =========================== GEMM kernels (as R8) ==========================
#define LDS_B   80
#define A_TILE  10240
#define B_TILE128 10240
#define G_BUFSZ (2 * A_TILE + 2 * B_TILE128)   // 40960

__device__ __forceinline__ void cp_tile128(
    uint32_t sm_hi, uint32_t sm_lo,
    const __nv_bfloat16* __restrict__ ghi, const __nv_bfloat16* __restrict__ glo,
    int ld, int tid)
{
#pragma unroll
    for (int it = 0; it < 4; ++it) {
        int idx = tid + 256 * it;
        int mat = idx >> 9;
        int r   = (idx >> 2) & 127;
        int c   = idx & 3;
        uint32_t dst = (mat ? sm_lo : sm_hi) + (uint32_t)(r * LDS_B + c * 16);
        const __nv_bfloat16* src = (mat ? glo : ghi) + (size_t)r * ld + c * 8;
        CP16(dst, src);
    }
}

template <int NF>
__device__ __forceinline__ void compute_ktile(
    uint32_t aHi, uint32_t aLo, uint32_t bHi, uint32_t bLo,
    int m0, int n0, int lane, float (&acc)[4][NF][4])
{
#pragma unroll
    for (int ks = 0; ks < 2; ++ks) {
        const uint32_t acol = (uint32_t)(ks * 32 + (lane >> 4) * 16);
        const uint32_t bcol = (uint32_t)(ks * 32 + ((lane >> 3) & 1) * 16);
        const int arow = m0 + (lane & 15);
        const int brow = n0 + 8 * (lane >> 4) + (lane & 7);

        uint32_t ah[4][4], bh[NF][2], bl[NF][2];
#pragma unroll
        for (int i = 0; i < 4; ++i) {
            uint32_t ad = aHi + (uint32_t)((arow + 16 * i) * LDS_B) + acol;
            LDMX4(ah[i][0], ah[i][1], ah[i][2], ah[i][3], ad);
        }
#pragma unroll
        for (int j = 0; j < NF; j += 2) {
            uint32_t off = (uint32_t)((brow + 8 * j) * LDS_B) + bcol;
            LDMX4(bh[j][0], bh[j][1], bh[j + 1][0], bh[j + 1][1], bHi + off);
            LDMX4(bl[j][0], bl[j][1], bl[j + 1][0], bl[j + 1][1], bLo + off);
        }
#pragma unroll
        for (int i = 0; i < 4; ++i)
#pragma unroll
            for (int j = 0; j < NF; ++j) {
                mma16816(acc[i][j], ah[i][0], ah[i][1], ah[i][2], ah[i][3],
                         bh[j][0], bh[j][1]);
                mma16816(acc[i][j], ah[i][0], ah[i][1], ah[i][2], ah[i][3],
                         bl[j][0], bl[j][1]);
            }
#pragma unroll
        for (int i = 0; i < 4; ++i) {
            uint32_t al[4];
            uint32_t ad = aLo + (uint32_t)((arow + 16 * i) * LDS_B) + acol;
            LDMX4(al[0], al[1], al[2], al[3], ad);
#pragma unroll
            for (int j = 0; j < NF; ++j)
                mma16816(acc[i][j], al[0], al[1], al[2], al[3],
                         bh[j][0], bh[j][1]);
        }
    }
}

// mode 0: qkv  (x hi/lo @ w_qkv hi/lo -> g_qkv hi/lo)
// mode 2: proj (attn hi/lo @ w_out hi/lo -> out fp32 + bias)
__global__ void __launch_bounds__(256) mma_gemm(int mode,
                                                const float* __restrict__ bias,
                                                float* __restrict__ outp)
{
    extern __shared__ char smem[];
    const int tid  = threadIdx.x;
    const int wid  = tid >> 5, lane = tid & 31;
    const int m0   = (wid >> 2) * 64;
    const int n0   = (wid & 3) * 32;
    const uint32_t sb = smem_u32(smem);

    const int bm = blockIdx.y * 128, bn = blockIdx.x * 128;

    const __nv_bfloat16 *ahi, *alo, *bhi, *blo;
    if (mode == 0) {
        ahi = g_x_hi + (size_t)bm * CDIM;  alo = g_x_lo + (size_t)bm * CDIM;
        bhi = g_wqkv_hi + (size_t)bn * CDIM; blo = g_wqkv_lo + (size_t)bn * CDIM;
    } else {
        ahi = g_attn_hi + (size_t)bm * CDIM; alo = g_attn_lo + (size_t)bm * CDIM;
        bhi = g_wout_hi + (size_t)bn * CDIM; blo = g_wout_lo + (size_t)bn * CDIM;
    }
    const int K = CDIM;

    const uint32_t sAhi[2] = {sb,            sb + G_BUFSZ};
    const uint32_t sAlo[2] = {sb + A_TILE,   sb + G_BUFSZ + A_TILE};
    const uint32_t sBhi[2] = {sb + 2*A_TILE, sb + G_BUFSZ + 2*A_TILE};
    const uint32_t sBlo[2] = {sb + 2*A_TILE + B_TILE128,
                              sb + G_BUFSZ + 2*A_TILE + B_TILE128};

    float acc[4][4][4];
#pragma unroll
    for (int i = 0; i < 4; ++i)
#pragma unroll
        for (int j = 0; j < 4; ++j)
#pragma unroll
            for (int k = 0; k < 4; ++k) acc[i][j][k] = 0.0f;

    const int nt = K >> 5;
    cp_tile128(sAhi[0], sAlo[0], ahi, alo, CDIM, tid);
    cp_tile128(sBhi[0], sBlo[0], bhi, blo, CDIM, tid);
    CP_COMMIT();

    for (int t = 0; t < nt; ++t) {
        const int bf = t & 1;
        if (t + 1 < nt) {
            const int nb = (t + 1) & 1, k0 = (t + 1) << 5;
            cp_tile128(sAhi[nb], sAlo[nb], ahi + k0, alo + k0, CDIM, tid);
            cp_tile128(sBhi[nb], sBlo[nb], bhi + k0, blo + k0, CDIM, tid);
            CP_COMMIT();
            CP_WAIT1();
        } else {
            CP_WAIT0();
        }
        __syncthreads();
        compute_ktile<4>(sAhi[bf], sAlo[bf], sBhi[bf], sBlo[bf], m0, n0, lane, acc);
        __syncthreads();
    }

    if (mode == 2) {
#pragma unroll
        for (int i = 0; i < 4; ++i) {
            const int r0 = bm + m0 + 16 * i + (lane >> 2);
#pragma unroll
            for (int j = 0; j < 4; ++j) {
                const int col = bn + n0 + 8 * j + (lane & 3) * 2;
                float b0 = bias[col], b1 = bias[col + 1];
                *(float2*)(outp + (size_t)r0 * CDIM + col) =
                    make_float2(acc[i][j][0] + b0, acc[i][j][1] + b1);
                *(float2*)(outp + (size_t)(r0 + 8) * CDIM + col) =
                    make_float2(acc[i][j][2] + b0, acc[i][j][3] + b1);
            }
        }
    } else {
#pragma unroll
        for (int i = 0; i < 4; ++i) {
            const int r0 = bm + m0 + 16 * i + (lane >> 2);
#pragma unroll
            for (int j = 0; j < 4; ++j) {
                const int col = bn + n0 + 8 * j + (lane & 3) * 2;
                __nv_bfloat16 h0, h1, l0, l1;
#pragma unroll
                for (int half = 0; half < 2; ++half) {
                    cvt_hilo(acc[i][j][2 * half + 0], h0, l0);
                    cvt_hilo(acc[i][j][2 * half + 1], h1, l1);
                    const size_t off = (size_t)(r0 + 8 * half) * F3 + col;
                    *(uint32_t*)(g_qkv_hi + off) = pk(h0, h1);
                    *(uint32_t*)(g_qkv_lo + off) = pk(l0, l1);
                }
            }
        }
    }
}

// ======================= Fused flash attention =============================
// Per CTA: 128 q-rows of one (b,h). Loop over 2048 keys in 64-key tiles.
// smem: Q hi/lo (128x64, 144B stride) + 2x K hi/lo (64x64) + 2x V^T hi/lo.
#define FL_STRIDE 144
#define FL_Q      18432              // 128*144
#define FL_KV     9216               // 64*144
#define FL_KBASE  (2 * FL_Q)         // 36864
#define FL_VBASE  (FL_KBASE + 4 * FL_KV)  // 73728
#define FL_SMEM   (FL_VBASE + 4 * FL_KV)  // 110592

__global__ void __launch_bounds__(256) flash_kernel()
{
    extern __shared__ char smem[];
    const int tid = threadIdx.x, wid = tid >> 5, lane = tid & 31;
    const uint32_t sb = smem_u32(smem);
    const int z = blockIdx.y, b = z >> 4, h = z & 15;
    const int bm = blockIdx.x * 128;
    const int wm = wid * 16;             // warp's 16 q rows

    const size_t qoff = (size_t)(b * SEQ + bm) * F3 + (size_t)h * HD;
    const __nv_bfloat16* qhg = g_qkv_hi + qoff;
    const __nv_bfloat16* qlg = g_qkv_lo + qoff;
    const size_t kbase = (size_t)b * SEQ * F3 + CDIM + (size_t)h * HD;
    const __nv_bfloat16* khg = g_qkv_hi + kbase;
    const __nv_bfloat16* klg = g_qkv_lo + kbase;
    const size_t vbase = (size_t)b * SEQ * F3 + 2 * CDIM + (size_t)h * HD;
    const __nv_bfloat16* vhg = g_qkv_hi + vbase;
    const __nv_bfloat16* vlg = g_qkv_lo + vbase;

    const uint32_t SQH = sb, SQL = sb + FL_Q;

    // ---- Q cp.async (group 0)
#pragma unroll
    for (int it = 0; it < 8; ++it) {
        int idx = tid + 256 * it;
        int mat = idx >> 10, r = (idx >> 3) & 127, c = idx & 7;
        uint32_t dst = (mat ? SQL : SQH) + (uint32_t)(r * FL_STRIDE + c * 16);
        const __nv_bfloat16* src = (mat ? qlg : qhg) + (size_t)r * F3 + c * 8;
        CP16(dst, src);
    }
    CP_COMMIT();

    // ---- K tile 0 (group 1)
    auto cp_k = [&](int buf, int key0) {
        uint32_t base = sb + FL_KBASE + (uint32_t)buf * 2 * FL_KV;
#pragma unroll
        for (int it = 0; it < 4; ++it) {
            int idx = tid + 256 * it;
            int mat = idx >> 9, r = (idx >> 3) & 63, c = idx & 7;
            uint32_t dst = base + (uint32_t)(mat * FL_KV + r * FL_STRIDE + c * 16);
            const __nv_bfloat16* src = (mat ? klg : khg) + (size_t)(key0 + r) * F3 + c * 8;
            CP16(dst, src);
        }
    };
    uint2 vr[8];
    auto ld_v = [&](int key0) {
#pragma unroll
        for (int it = 0; it < 8; ++it) {
            int idx = tid + 256 * it;
            int mat = idx >> 10, rem = idx & 1023, key = rem >> 4, dg = rem & 15;
            vr[it] = *(const uint2*)((mat ? vlg : vhg) + (size_t)(key0 + key) * F3 + dg * 4);
        }
    };
    auto st_v = [&](int buf) {
        uint32_t base = sb + FL_VBASE + (uint32_t)buf * 2 * FL_KV;
#pragma unroll
        for (int it = 0; it < 8; ++it) {
            int idx = tid + 256 * it;
            int mat = idx >> 10, rem = idx & 1023, key = rem >> 4, dg = rem & 15;
            uint32_t t = base + (uint32_t)(mat * FL_KV);
            unsigned short e[4] = {
                (unsigned short)vr[it].x, (unsigned short)(vr[it].x >> 16),
                (unsigned short)vr[it].y, (unsigned short)(vr[it].y >> 16)};
#pragma unroll
            for (int j = 0; j < 4; ++j)
                asm volatile("st.shared.u16 [%0], %1;"
                             :: "r"(t + (uint32_t)((dg * 4 + j) * FL_STRIDE + key * 2)),
                                "h"(e[j]));
        }
    };

    cp_k(0, 0);
    CP_COMMIT();
    ld_v(0);
    CP_WAIT1();                       // Q done
    __syncthreads();
    st_v(0);

    // ---- Q fragments (resident)
    uint32_t qh[4][4], ql[4][4];
    {
        const uint32_t arow = (uint32_t)((wm + (lane & 15)) * FL_STRIDE + (lane >> 4) * 16);
#pragma unroll
        for (int ks = 0; ks < 4; ++ks) {
            LDMX4(qh[ks][0], qh[ks][1], qh[ks][2], qh[ks][3], SQH + arow + ks * 32);
            LDMX4(ql[ks][0], ql[ks][1], ql[ks][2], ql[ks][3], SQL + arow + ks * 32);
        }
    }

    float acco[8][4];
#pragma unroll
    for (int j = 0; j < 8; ++j)
#pragma unroll
        for (int k = 0; k < 4; ++k) acco[j][k] = 0.0f;
    float mr0 = -1e30f, mr1 = -1e30f, lr0 = 0.0f, lr1 = 0.0f;

    const uint32_t boff = (uint32_t)((8 * (lane >> 4) + (lane & 7)) * FL_STRIDE
                                     + ((lane >> 3) & 1) * 16);

    const int NT = SEQ / 64;  // 32
    for (int t = 0; t < NT; ++t) {
        const int bf = t & 1;
        if (t + 1 < NT) {
            cp_k(1 - bf, (t + 1) * 64);
            CP_COMMIT();
            ld_v((t + 1) * 64);
            CP_WAIT1();
        } else {
            CP_WAIT0();
        }
        __syncthreads();

        // ---- S = Q @ K^T (3-pass)
        const uint32_t khb = sb + FL_KBASE + (uint32_t)bf * 2 * FL_KV;
        const uint32_t klb = khb + FL_KV;
        float accs[8][4];
#pragma unroll
        for (int j = 0; j < 8; ++j)
#pragma unroll
            for (int k = 0; k < 4; ++k) accs[j][k] = 0.0f;
#pragma unroll
        for (int ks = 0; ks < 4; ++ks) {
#pragma unroll
            for (int jp = 0; jp < 4; ++jp) {
                uint32_t off = boff + (uint32_t)(jp * 16 * FL_STRIDE + ks * 32);
                uint32_t h0, h1, h2, h3, e0, e1, e2, e3;
                LDMX4(h0, h1, h2, h3, khb + off);
                LDMX4(e0, e1, e2, e3, klb + off);
                mma16816(accs[2*jp],   qh[ks][0], qh[ks][1], qh[ks][2], qh[ks][3], h0, h1);
                mma16816(accs[2*jp+1], qh[ks][0], qh[ks][1], qh[ks][2], qh[ks][3], h2, h3);
                mma16816(accs[2*jp],   qh[ks][0], qh[ks][1], qh[ks][2], qh[ks][3], e0, e1);
                mma16816(accs[2*jp+1], qh[ks][0], qh[ks][1], qh[ks][2], qh[ks][3], e2, e3);
                mma16816(accs[2*jp],   ql[ks][0], ql[ks][1], ql[ks][2], ql[ks][3], h0, h1);
                mma16816(accs[2*jp+1], ql[ks][0], ql[ks][1], ql[ks][2], ql[ks][3], h2, h3);
            }
        }

        // ---- online softmax
        float rm0 = -1e30f, rm1 = -1e30f;
#pragma unroll
        for (int j = 0; j < 8; ++j) {
            accs[j][0] *= ATTN_SCALE; accs[j][1] *= ATTN_SCALE;
            accs[j][2] *= ATTN_SCALE; accs[j][3] *= ATTN_SCALE;
            rm0 = fmaxf(rm0, fmaxf(accs[j][0], accs[j][1]));
            rm1 = fmaxf(rm1, fmaxf(accs[j][2], accs[j][3]));
        }
        rm0 = fmaxf(rm0, __shfl_xor_sync(0xffffffffu, rm0, 1));
        rm0 = fmaxf(rm0, __shfl_xor_sync(0xffffffffu, rm0, 2));
        rm1 = fmaxf(rm1, __shfl_xor_sync(0xffffffffu, rm1, 1));
        rm1 = fmaxf(rm1, __shfl_xor_sync(0xffffffffu, rm1, 2));
        const float mn0 = fmaxf(mr0, rm0), mn1 = fmaxf(mr1, rm1);
        const float al0 = __expf(mr0 - mn0), al1 = __expf(mr1 - mn1);
        mr0 = mn0; mr1 = mn1;

        float s0 = 0.0f, s1 = 0.0f;
        uint32_t pah[4][4], pal[4][4];
#pragma unroll
        for (int j = 0; j < 8; ++j) {
            float p0 = __expf(accs[j][0] - mn0);
            float p1 = __expf(accs[j][1] - mn0);
            float p2 = __expf(accs[j][2] - mn1);
            float p3 = __expf(accs[j][3] - mn1);
            s0 += p0 + p1; s1 += p2 + p3;
            __nv_bfloat16 h0b, l0b, h1b, l1b, h2b, l2b, h3b, l3b;
            cvt_hilo(p0, h0b, l0b); cvt_hilo(p1, h1b, l1b);
            cvt_hilo(p2, h2b, l2b); cvt_hilo(p3, h3b, l3b);
            const int ks = j >> 1;
            if ((j & 1) == 0) {
                pah[ks][0] = pk(h0b, h1b); pah[ks][1] = pk(h2b, h3b);
                pal[ks][0] = pk(l0b, l1b); pal[ks][1] = pk(l2b, l3b);
            } else {
                pah[ks][2] = pk(h0b, h1b); pah[ks][3] = pk(h2b, h3b);
                pal[ks][2] = pk(l0b, l1b); pal[ks][3] = pk(l2b, l3b);
            }
        }
        s0 += __shfl_xor_sync(0xffffffffu, s0, 1);
        s0 += __shfl_xor_sync(0xffffffffu, s0, 2);
        s1 += __shfl_xor_sync(0xffffffffu, s1, 1);
        s1 += __shfl_xor_sync(0xffffffffu, s1, 2);
        lr0 = lr0 * al0 + s0; lr1 = lr1 * al1 + s1;
#pragma unroll
        for (int j = 0; j < 8; ++j) {
            acco[j][0] *= al0; acco[j][1] *= al0;
            acco[j][2] *= al1; acco[j][3] *= al1;
        }

        // ---- O += P @ V (3-pass), V^T resident as [d][key]
        const uint32_t vhb = sb + FL_VBASE + (uint32_t)bf * 2 * FL_KV;
        const uint32_t vlb = vhb + FL_KV;
#pragma unroll
        for (int ks = 0; ks < 4; ++ks) {
#pragma unroll
            for (int jp = 0; jp < 4; ++jp) {
                uint32_t off = boff + (uint32_t)(jp * 16 * FL_STRIDE + ks * 32);
                uint32_t h0, h1, h2, h3, e0, e1, e2, e3;
                LDMX4(h0, h1, h2, h3, vhb + off);
                LDMX4(e0, e1, e2, e3, vlb + off);
                mma16816(acco[2*jp],   pah[ks][0], pah[ks][1], pah[ks][2], pah[ks][3], h0, h1);
                mma16816(acco[2*jp+1], pah[ks][0], pah[ks][1], pah[ks][2], pah[ks][3], h2, h3);
                mma16816(acco[2*jp],   pah[ks][0], pah[ks][1], pah[ks][2], pah[ks][3], e0, e1);
                mma16816(acco[2*jp+1], pah[ks][0], pah[ks][1], pah[ks][2], pah[ks][3], e2, e3);
                mma16816(acco[2*jp],   pal[ks][0], pal[ks][1], pal[ks][2], pal[ks][3], h0, h1);
                mma16816(acco[2*jp+1], pal[ks][0], pal[ks][1], pal[ks][2], pal[ks][3], h2, h3);
            }
        }

        if (t + 1 < NT) st_v(1 - bf);
        __syncthreads();
    }

    // ---- epilogue: O / l -> attn hi/lo
    const float inv0 = 1.0f / lr0, inv1 = 1.0f / lr1;
    const int rg = b * SEQ + bm + wm + (lane >> 2);
#pragma unroll
    for (int j = 0; j < 8; ++j) {
        const int col = h * HD + j * 8 + (lane & 3) * 2;
        __nv_bfloat16 h0b, l0b, h1b, l1b;
        cvt_hilo(acco[j][0] * inv0, h0b, l0b);
        cvt_hilo(acco[j][1] * inv0, h1b, l1b);
        size_t off = (size_t)rg * CDIM + col;
        *(uint32_t*)(g_attn_hi + off) = pk(h0b, h1b);
        *(uint32_t*)(g_attn_lo + off) = pk(l0b, l1b);
        cvt_hilo(acco[j][2] * inv1, h0b, l0b);
        cvt_hilo(acco[j][3] * inv1, h1b, l1b);
        off = (size_t)(rg + 8) * CDIM + col;
        *(uint32_t*)(g_attn_hi + off) = pk(h0b, h1b);
        *(uint32_t*)(g_attn_lo + off) = pk(l0b, l1b);
    }
}

// ---------------------------------------------------------------------------
// fp32 -> bf16 hi/lo elementwise convert
// ---------------------------------------------------------------------------
__global__ void __launch_bounds__(256) cvt_kernel(
    const float4* __restrict__ src, uint2* __restrict__ hi,
    uint2* __restrict__ lo, int n4)
{
    int i = blockIdx.x * blockDim.x + threadIdx.x;
    if (i >= n4) return;
    float4 v = src[i];
    __nv_bfloat16 h0, h1, h2, h3, l0, l1, l2, l3;
    cvt_hilo(v.x, h0, l0); cvt_hilo(v.y, h1, l1);
    cvt_hilo(v.z, h2, l2); cvt_hilo(v.w, h3, l3);
    hi[i] = make_uint2(pk(h0, h1), pk(h2, h3));
    lo[i] = make_uint2(pk(l0, l1), pk(l2, l3));
}

// ---------------------------------------------------------------------------
extern "C" void kernel_launch(void* const* d_in, const int* in_sizes, int n_in,
                              void* d_out, int out_size)
{
    (void)in_sizes; (void)n_in; (void)out_size;
    const float* x     = (const float*)d_in[0];
    const float* w_qkv = (const float*)d_in[1];
    const float* w_out = (const float*)d_in[2];
    const float* b_out = (const float*)d_in[3];
    float* out = (float*)d_out;

    static int attr_done = 0;
    if (!attr_done) {
        cudaFuncSetAttribute(mma_gemm, cudaFuncAttributeMaxDynamicSharedMemorySize,
                             2 * G_BUFSZ);
        cudaFuncSetAttribute(flash_kernel, cudaFuncAttributeMaxDynamicSharedMemorySize,
                             FL_SMEM);
        attr_done = 1;
    }

    __nv_bfloat16 *xh, *xl, *qh, *ql, *oh, *ol;
    cudaGetSymbolAddress((void**)&xh, g_x_hi);
    cudaGetSymbolAddress((void**)&xl, g_x_lo);
    cudaGetSymbolAddress((void**)&qh, g_wqkv_hi);
    cudaGetSymbolAddress((void**)&ql, g_wqkv_lo);
    cudaGetSymbolAddress((void**)&oh, g_wout_hi);
    cudaGetSymbolAddress((void**)&ol, g_wout_lo);

    {
        int n4 = MROWS * CDIM / 4;
        cvt_kernel<<<(n4 + 255) / 256, 256>>>((const float4*)x, (uint2*)xh, (uint2*)xl, n4);
        n4 = F3 * CDIM / 4;
        cvt_kernel<<<(n4 + 255) / 256, 256>>>((const float4*)w_qkv, (uint2*)qh, (uint2*)ql, n4);
        n4 = CDIM * CDIM / 4;
        cvt_kernel<<<(n4 + 255) / 256, 256>>>((const float4*)w_out, (uint2*)oh, (uint2*)ol, n4);
    }

    // 1) QKV -> g_qkv hi/lo
    mma_gemm<<<dim3(F3 / 128, MROWS / 128), 256, 2 * G_BUFSZ>>>(0, nullptr, nullptr);
    // 2) fused flash attention -> g_attn hi/lo
    flash_kernel<<<dim3(SEQ / 128, NBH), 256, FL_SMEM>>>();
    // 3) proj -> out (+bias)
    mma_gemm<<<dim3(CDIM / 128, MROWS / 128), 256, 2 * G_BUFSZ>>>(2, b_out, out);
}

// round 10
// speedup vs baseline: 2.6891x; 1.2464x over previous
#include <cuda_runtime.h>
#include <cuda_bf16.h>
#include <cstdint>

#define BATCH 2
#define SEQ   2048
#define CDIM  1024
#define NH    16
#define HD    64
#define MROWS (BATCH * SEQ)      // 4096
#define F3    (3 * CDIM)         // 3072
#define ATTN_SCALE 0.125f
#define NBH   (BATCH * NH)       // 32

// ---------------------------------------------------------------------------
// Static scratch (allocation-free)
// ---------------------------------------------------------------------------
__device__ __nv_bfloat16 g_x_hi[(size_t)MROWS * CDIM];
__device__ __nv_bfloat16 g_x_lo[(size_t)MROWS * CDIM];
__device__ __nv_bfloat16 g_wqkv_hi[(size_t)F3 * CDIM];
__device__ __nv_bfloat16 g_wqkv_lo[(size_t)F3 * CDIM];
__device__ __nv_bfloat16 g_wout_hi[(size_t)CDIM * CDIM];
__device__ __nv_bfloat16 g_wout_lo[(size_t)CDIM * CDIM];
__device__ __nv_bfloat16 g_qkv_hi[(size_t)MROWS * F3];   // Q part pre-scaled by 0.125
__device__ __nv_bfloat16 g_qkv_lo[(size_t)MROWS * F3];
__device__ __nv_bfloat16 g_attn_hi[(size_t)MROWS * CDIM];
__device__ __nv_bfloat16 g_attn_lo[(size_t)MROWS * CDIM];

// ---------------------------------------------------------------------------
// Helpers
// ---------------------------------------------------------------------------
__device__ __forceinline__ uint32_t smem_u32(const void* p) {
    uint32_t a;
    asm("{ .reg .u64 t; cvta.to.shared.u64 t, %1; cvt.u32.u64 %0, t; }"
        : "=r"(a) : "l"(p));
    return a;
}
__device__ __forceinline__ void cvt_hilo(float x, __nv_bfloat16& h, __nv_bfloat16& l) {
    h = __float2bfloat16(x);
    l = __float2bfloat16(x - __bfloat162float(h));
}
__device__ __forceinline__ uint32_t pk(__nv_bfloat16 a, __nv_bfloat16 b) {
    return (uint32_t)__bfloat16_as_ushort(a) | ((uint32_t)__bfloat16_as_ushort(b) << 16);
}

#define LDMX4(r0, r1, r2, r3, addr)                                            \
    asm volatile("ldmatrix.sync.aligned.m8n8.x4.shared.b16 {%0,%1,%2,%3}, [%4];" \
                 : "=r"(r0), "=r"(r1), "=r"(r2), "=r"(r3) : "r"(addr))
#define LDMX4T(r0, r1, r2, r3, addr)                                           \
    asm volatile("ldmatrix.sync.aligned.m8n8.x4.trans.shared.b16 {%0,%1,%2,%3}, [%4];" \
                 : "=r"(r0), "=r"(r1), "=r"(r2), "=r"(r3) : "r"(addr))

__device__ __forceinline__ void mma16816(float* c, uint32_t a0, uint32_t a1,
                                         uint32_t a2, uint32_t a3,
                                         uint32_t b0, uint32_t b1) {
    asm volatile(
        "mma.sync.aligned.m16n8k16.row.col.f32.bf16.bf16.f32 "
        "{%0,%1,%2,%3}, {%4,%5,%6,%7}, {%8,%9}, {%0,%1,%2,%3};"
        : "+f"(c[0]), "+f"(c[1]), "+f"(c[2]), "+f"(c[3])
        : "r"(a0), "r"(a1), "r"(a2), "r"(a3), "r"(b0), "r"(b1));
}

#define CP16(dst, src) \
    asm volatile("cp.async.cg.shared.global [%0], [%1], 16;" :: "r"(dst), "l"(src))
#define CP_COMMIT() asm volatile("cp.async.commit_group;" ::: "memory")
#define CP_WAIT1()  asm volatile("cp.async.wait_group 1;" ::: "memory")
#define CP_WAIT0()  asm volatile("cp.async.wait_group 0;" ::: "memory")

// ============================ Big GEMM kernel ==============================
// CTA tile 128(M) x 256(N), BK=64, 8 warps (2x4), warp tile 64x64.
// 3-pass hi/lo bf16 mma. 1 CTA/SM (216KB smem, double buffered).
#define GM_ST    144
#define GM_A     18432            // 128 * 144
#define GM_B     36864            // 256 * 144
#define GM_BUF   (2 * GM_A + 2 * GM_B)   // 110592
// layout per buffer: [A_HI][A_LO][B_HI][B_LO]

__global__ void __launch_bounds__(256) mma_gemm(int mode,
                                                const float* __restrict__ bias,
                                                float* __restrict__ outp)
{
    extern __shared__ char smem[];
    const int tid  = threadIdx.x;
    const int wid  = tid >> 5, lane = tid & 31;
    const int m0   = (wid >> 2) * 64;    // 0 or 64
    const int n0   = (wid & 3) * 64;     // 0,64,128,192
    const uint32_t sb = smem_u32(smem);

    const int bm = blockIdx.y * 128, bn = blockIdx.x * 256;

    const __nv_bfloat16 *ahi, *alo, *bhi, *blo;
    if (mode == 0) {
        ahi = g_x_hi + (size_t)bm * CDIM;    alo = g_x_lo + (size_t)bm * CDIM;
        bhi = g_wqkv_hi + (size_t)bn * CDIM; blo = g_wqkv_lo + (size_t)bn * CDIM;
    } else {
        ahi = g_attn_hi + (size_t)bm * CDIM; alo = g_attn_lo + (size_t)bm * CDIM;
        bhi = g_wout_hi + (size_t)bn * CDIM; blo = g_wout_lo + (size_t)bn * CDIM;
    }

    auto cp_a = [&](int buf, int k0) {
        uint32_t base = sb + (uint32_t)buf * GM_BUF;
#pragma unroll
        for (int it = 0; it < 8; ++it) {
            int idx = tid + 256 * it;            // 0..2047
            int mat = idx >> 10, r = (idx >> 3) & 127, c = idx & 7;
            uint32_t dst = base + (uint32_t)(mat * GM_A + r * GM_ST + c * 16);
            const __nv_bfloat16* src = (mat ? alo : ahi) + (size_t)r * CDIM + k0 + c * 8;
            CP16(dst, src);
        }
    };
    auto cp_b = [&](int buf, int k0) {
        uint32_t base = sb + (uint32_t)buf * GM_BUF + 2 * GM_A;
#pragma unroll
        for (int it = 0; it < 16; ++it) {
            int idx = tid + 256 * it;            // 0..4095
            int mat = idx >> 11, r = (idx >> 3) & 255, c = idx & 7;
            uint32_t dst = base + (uint32_t)(mat * GM_B + r * GM_ST + c * 16);
            const __nv_bfloat16* src = (mat ? blo : bhi) + (size_t)r * CDIM + k0 + c * 8;
            CP16(dst, src);
        }
    };

    float acc[4][8][4];
#pragma unroll
    for (int i = 0; i < 4; ++i)
#pragma unroll
        for (int j = 0; j < 8; ++j)
#pragma unroll
            for (int k = 0; k < 4; ++k) acc[i][j][k] = 0.0f;

    const int nt = CDIM / 64;   // 16
    cp_a(0, 0); cp_b(0, 0); CP_COMMIT();

    for (int t = 0; t < nt; ++t) {
        const int bf = t & 1;
        if (t + 1 < nt) {
            const int nb = 1 - bf, k0 = (t + 1) * 64;
            cp_a(nb, k0); cp_b(nb, k0); CP_COMMIT();
            CP_WAIT1();
        } else {
            CP_WAIT0();
        }
        __syncthreads();

        const uint32_t aH = sb + (uint32_t)bf * GM_BUF;
        const uint32_t aL = aH + GM_A;
        const uint32_t bH = aH + 2 * GM_A;
        const uint32_t bL = bH + GM_B;
        const uint32_t arow = (uint32_t)((m0 + (lane & 15)) * GM_ST + (lane >> 4) * 16);
        const uint32_t brow = (uint32_t)((n0 + 8 * (lane >> 4) + (lane & 7)) * GM_ST
                                         + ((lane >> 3) & 1) * 16);

#pragma unroll
        for (int ks = 0; ks < 4; ++ks) {
            const uint32_t kadd = (uint32_t)(ks * 32);
            uint32_t ah[4][4], al[4][4];
#pragma unroll
            for (int i = 0; i < 4; ++i) {
                uint32_t ao = arow + (uint32_t)(i * 16 * GM_ST) + kadd;
                LDMX4(ah[i][0], ah[i][1], ah[i][2], ah[i][3], aH + ao);
                LDMX4(al[i][0], al[i][1], al[i][2], al[i][3], aL + ao);
            }
#pragma unroll
            for (int half = 0; half < 2; ++half) {
                uint32_t bh[4][2], bl[4][2];
#pragma unroll
                for (int jj = 0; jj < 2; ++jj) {
                    uint32_t bo = brow + (uint32_t)((half * 32 + jj * 16) * GM_ST) + kadd;
                    LDMX4(bh[2*jj][0], bh[2*jj][1], bh[2*jj+1][0], bh[2*jj+1][1], bH + bo);
                    LDMX4(bl[2*jj][0], bl[2*jj][1], bl[2*jj+1][0], bl[2*jj+1][1], bL + bo);
                }
#pragma unroll
                for (int i = 0; i < 4; ++i)
#pragma unroll
                    for (int j = 0; j < 4; ++j) {
                        float* a = acc[i][half * 4 + j];
                        mma16816(a, ah[i][0], ah[i][1], ah[i][2], ah[i][3],
                                 bh[j][0], bh[j][1]);
                        mma16816(a, ah[i][0], ah[i][1], ah[i][2], ah[i][3],
                                 bl[j][0], bl[j][1]);
                        mma16816(a, al[i][0], al[i][1], al[i][2], al[i][3],
                                 bh[j][0], bh[j][1]);
                    }
            }
        }
        __syncthreads();
    }

    if (mode == 2) {
#pragma unroll
        for (int i = 0; i < 4; ++i) {
            const int r0 = bm + m0 + 16 * i + (lane >> 2);
#pragma unroll
            for (int j = 0; j < 8; ++j) {
                const int col = bn + n0 + 8 * j + (lane & 3) * 2;
                float b0 = bias[col], b1 = bias[col + 1];
                *(float2*)(outp + (size_t)r0 * CDIM + col) =
                    make_float2(acc[i][j][0] + b0, acc[i][j][1] + b1);
                *(float2*)(outp + (size_t)(r0 + 8) * CDIM + col) =
                    make_float2(acc[i][j][2] + b0, acc[i][j][3] + b1);
            }
        }
    } else {
        // QKV epilogue: pre-scale Q region (cols < 1024) by ATTN_SCALE (exact)
        const float scale = ((bn + n0) < CDIM) ? ATTN_SCALE : 1.0f;
#pragma unroll
        for (int i = 0; i < 4; ++i) {
            const int r0 = bm + m0 + 16 * i + (lane >> 2);
#pragma unroll
            for (int j = 0; j < 8; ++j) {
                const int col = bn + n0 + 8 * j + (lane & 3) * 2;
                __nv_bfloat16 h0, h1, l0, l1;
#pragma unroll
                for (int half = 0; half < 2; ++half) {
                    cvt_hilo(acc[i][j][2 * half + 0] * scale, h0, l0);
                    cvt_hilo(acc[i][j][2 * half + 1] * scale, h1, l1);
                    const size_t off = (size_t)(r0 + 8 * half) * F3 + col;
                    *(uint32_t*)(g_qkv_hi + off) = pk(h0, h1);
                    *(uint32_t*)(g_qkv_lo + off) = pk(l0, l1);
                }
            }
        }
    }
}

// ======================= Fused flash attention =============================
// Per CTA: 128 q-rows of one (b,h). 64-key tiles, K and V both cp.async
// row-major [key][d]; V B-fragments via ldmatrix.trans (no manual transpose).
#define FL_STRIDE 144
#define FL_Q      18432              // 128*144
#define FL_KV     9216               // 64*144
#define FL_KBASE  (2 * FL_Q)         // 36864
#define FL_VBASE  (FL_KBASE + 4 * FL_KV)  // 73728
#define FL_SMEM   (FL_VBASE + 4 * FL_KV)  // 110592

__global__ void __launch_bounds__(256) flash_kernel()
{
    extern __shared__ char smem[];
    const int tid = threadIdx.x, wid = tid >> 5, lane = tid & 31;
    const uint32_t sb = smem_u32(smem);
    const int z = blockIdx.y, b = z >> 4, h = z & 15;
    const int bm = blockIdx.x * 128;
    const int wm = wid * 16;

    const size_t qoff = (size_t)(b * SEQ + bm) * F3 + (size_t)h * HD;
    const __nv_bfloat16* qhg = g_qkv_hi + qoff;
    const __nv_bfloat16* qlg = g_qkv_lo + qoff;
    const size_t kbase = (size_t)b * SEQ * F3 + CDIM + (size_t)h * HD;
    const __nv_bfloat16* khg = g_qkv_hi + kbase;
    const __nv_bfloat16* klg = g_qkv_lo + kbase;
    const size_t vbase = (size_t)b * SEQ * F3 + 2 * CDIM + (size_t)h * HD;
    const __nv_bfloat16* vhg = g_qkv_hi + vbase;
    const __nv_bfloat16* vlg = g_qkv_lo + vbase;

    const uint32_t SQH = sb, SQL = sb + FL_Q;

    // Q (group 0)
#pragma unroll
    for (int it = 0; it < 8; ++it) {
        int idx = tid + 256 * it;
        int mat = idx >> 10, r = (idx >> 3) & 127, c = idx & 7;
        uint32_t dst = (mat ? SQL : SQH) + (uint32_t)(r * FL_STRIDE + c * 16);
        const __nv_bfloat16* src = (mat ? qlg : qhg) + (size_t)r * F3 + c * 8;
        CP16(dst, src);
    }
    CP_COMMIT();

    auto cp_k = [&](int buf, int key0) {
        uint32_t base = sb + FL_KBASE + (uint32_t)buf * 2 * FL_KV;
#pragma unroll
        for (int it = 0; it < 4; ++it) {
            int idx = tid + 256 * it;
            int mat = idx >> 9, r = (idx >> 3) & 63, c = idx & 7;
            uint32_t dst = base + (uint32_t)(mat * FL_KV + r * FL_STRIDE + c * 16);
            const __nv_bfloat16* src = (mat ? klg : khg) + (size_t)(key0 + r) * F3 + c * 8;
            CP16(dst, src);
        }
    };
    auto cp_v = [&](int buf, int key0) {
        uint32_t base = sb + FL_VBASE + (uint32_t)buf * 2 * FL_KV;
#pragma unroll
        for (int it = 0; it < 4; ++it) {
            int idx = tid + 256 * it;
            int mat = idx >> 9, r = (idx >> 3) & 63, c = idx & 7;
            uint32_t dst = base + (uint32_t)(mat * FL_KV + r * FL_STRIDE + c * 16);
            const __nv_bfloat16* src = (mat ? vlg : vhg) + (size_t)(key0 + r) * F3 + c * 8;
            CP16(dst, src);
        }
    };

    cp_k(0, 0); cp_v(0, 0); CP_COMMIT();
    CP_WAIT1();                       // Q resident
    __syncthreads();

    // Q fragments (resident; Q already pre-scaled by 0.125)
    uint32_t qh[4][4], ql[4][4];
    {
        const uint32_t arow = (uint32_t)((wm + (lane & 15)) * FL_STRIDE + (lane >> 4) * 16);
#pragma unroll
        for (int ks = 0; ks < 4; ++ks) {
            LDMX4(qh[ks][0], qh[ks][1], qh[ks][2], qh[ks][3], SQH + arow + ks * 32);
            LDMX4(ql[ks][0], ql[ks][1], ql[ks][2], ql[ks][3], SQL + arow + ks * 32);
        }
    }

    float acco[8][4];
#pragma unroll
    for (int j = 0; j < 8; ++j)
#pragma unroll
        for (int k = 0; k < 4; ++k) acco[j][k] = 0.0f;
    float mr0 = -1e30f, mr1 = -1e30f, lr0 = 0.0f, lr1 = 0.0f;

    // K (B) fragment base offset: rows = keys, cols = d
    const uint32_t boff = (uint32_t)((8 * (lane >> 4) + (lane & 7)) * FL_STRIDE
                                     + ((lane >> 3) & 1) * 16);
    // V (B via trans) base offset: rows = keys, cols = d
    const uint32_t voff = (uint32_t)(((((lane >> 3) & 1) * 8) + (lane & 7)) * FL_STRIDE
                                     + (lane >> 4) * 16);

    const int NT = SEQ / 64;  // 32
    for (int t = 0; t < NT; ++t) {
        const int bf = t & 1;
        if (t + 1 < NT) {
            cp_k(1 - bf, (t + 1) * 64);
            cp_v(1 - bf, (t + 1) * 64);
            CP_COMMIT();
            CP_WAIT1();
        } else {
            CP_WAIT0();
        }
        __syncthreads();

        // ---- S = Q @ K^T (3-pass); Q pre-scaled
        const uint32_t khb = sb + FL_KBASE + (uint32_t)bf * 2 * FL_KV;
        const uint32_t klb = khb + FL_KV;
        float accs[8][4];
#pragma unroll
        for (int j = 0; j < 8; ++j)
#pragma unroll
            for (int k = 0; k < 4; ++k) accs[j][k] = 0.0f;
#pragma unroll
        for (int ks = 0; ks < 4; ++ks) {
#pragma unroll
            for (int jp = 0; jp < 4; ++jp) {
                uint32_t off = boff + (uint32_t)(jp * 16 * FL_STRIDE + ks * 32);
                uint32_t h0, h1, h2, h3, e0, e1, e2, e3;
                LDMX4(h0, h1, h2, h3, khb + off);
                LDMX4(e0, e1, e2, e3, klb + off);
                mma16816(accs[2*jp],   qh[ks][0], qh[ks][1], qh[ks][2], qh[ks][3], h0, h1);
                mma16816(accs[2*jp+1], qh[ks][0], qh[ks][1], qh[ks][2], qh[ks][3], h2, h3);
                mma16816(accs[2*jp],   qh[ks][0], qh[ks][1], qh[ks][2], qh[ks][3], e0, e1);
                mma16816(accs[2*jp+1], qh[ks][0], qh[ks][1], qh[ks][2], qh[ks][3], e2, e3);
                mma16816(accs[2*jp],   ql[ks][0], ql[ks][1], ql[ks][2], ql[ks][3], h0, h1);
                mma16816(accs[2*jp+1], ql[ks][0], ql[ks][1], ql[ks][2], ql[ks][3], h2, h3);
            }
        }

        // ---- online softmax
        float rm0 = -1e30f, rm1 = -1e30f;
#pragma unroll
        for (int j = 0; j < 8; ++j) {
            rm0 = fmaxf(rm0, fmaxf(accs[j][0], accs[j][1]));
            rm1 = fmaxf(rm1, fmaxf(accs[j][2], accs[j][3]));
        }
        rm0 = fmaxf(rm0, __shfl_xor_sync(0xffffffffu, rm0, 1));
        rm0 = fmaxf(rm0, __shfl_xor_sync(0xffffffffu, rm0, 2));
        rm1 = fmaxf(rm1, __shfl_xor_sync(0xffffffffu, rm1, 1));
        rm1 = fmaxf(rm1, __shfl_xor_sync(0xffffffffu, rm1, 2));
        const float mn0 = fmaxf(mr0, rm0), mn1 = fmaxf(mr1, rm1);
        const float al0 = __expf(mr0 - mn0), al1 = __expf(mr1 - mn1);
        mr0 = mn0; mr1 = mn1;

        float s0 = 0.0f, s1 = 0.0f;
        uint32_t pah[4][4], pal[4][4];
#pragma unroll
        for (int j = 0; j < 8; ++j) {
            float p0 = __expf(accs[j][0] - mn0);
            float p1 = __expf(accs[j][1] - mn0);
            float p2 = __expf(accs[j][2] - mn1);
            float p3 = __expf(accs[j][3] - mn1);
            s0 += p0 + p1; s1 += p2 + p3;
            __nv_bfloat16 h0b, l0b, h1b, l1b, h2b, l2b, h3b, l3b;
            cvt_hilo(p0, h0b, l0b); cvt_hilo(p1, h1b, l1b);
            cvt_hilo(p2, h2b, l2b); cvt_hilo(p3, h3b, l3b);
            const int ks = j >> 1;
            if ((j & 1) == 0) {
                pah[ks][0] = pk(h0b, h1b); pah[ks][1] = pk(h2b, h3b);
                pal[ks][0] = pk(l0b, l1b); pal[ks][1] = pk(l2b, l3b);
            } else {
                pah[ks][2] = pk(h0b, h1b); pah[ks][3] = pk(h2b, h3b);
                pal[ks][2] = pk(l0b, l1b); pal[ks][3] = pk(l2b, l3b);
            }
        }
        s0 += __shfl_xor_sync(0xffffffffu, s0, 1);
        s0 += __shfl_xor_sync(0xffffffffu, s0, 2);
        s1 += __shfl_xor_sync(0xffffffffu, s1, 1);
        s1 += __shfl_xor_sync(0xffffffffu, s1, 2);
        lr0 = lr0 * al0 + s0; lr1 = lr1 * al1 + s1;
#pragma unroll
        for (int j = 0; j < 8; ++j) {
            acco[j][0] *= al0; acco[j][1] *= al0;
            acco[j][2] *= al1; acco[j][3] *= al1;
        }

        // ---- O += P @ V (3-pass); V fragments via ldmatrix.trans
        const uint32_t vhb = sb + FL_VBASE + (uint32_t)bf * 2 * FL_KV;
        const uint32_t vlb = vhb + FL_KV;
#pragma unroll
        for (int ks = 0; ks < 4; ++ks) {
#pragma unroll
            for (int jp = 0; jp < 4; ++jp) {
                uint32_t off = voff + (uint32_t)(ks * 16 * FL_STRIDE + jp * 32);
                uint32_t h0, h1, h2, h3, e0, e1, e2, e3;
                LDMX4T(h0, h1, h2, h3, vhb + off);
                LDMX4T(e0, e1, e2, e3, vlb + off);
                mma16816(acco[2*jp],   pah[ks][0], pah[ks][1], pah[ks][2], pah[ks][3], h0, h1);
                mma16816(acco[2*jp+1], pah[ks][0], pah[ks][1], pah[ks][2], pah[ks][3], h2, h3);
                mma16816(acco[2*jp],   pah[ks][0], pah[ks][1], pah[ks][2], pah[ks][3], e0, e1);
                mma16816(acco[2*jp+1], pah[ks][0], pah[ks][1], pah[ks][2], pah[ks][3], e2, e3);
                mma16816(acco[2*jp],   pal[ks][0], pal[ks][1], pal[ks][2], pal[ks][3], h0, h1);
                mma16816(acco[2*jp+1], pal[ks][0], pal[ks][1], pal[ks][2], pal[ks][3], h2, h3);
            }
        }
        __syncthreads();
    }

    // ---- epilogue: O / l -> attn hi/lo
    const float inv0 = 1.0f / lr0, inv1 = 1.0f / lr1;
    const int rg = b * SEQ + bm + wm + (lane >> 2);
#pragma unroll
    for (int j = 0; j < 8; ++j) {
        const int col = h * HD + j * 8 + (lane & 3) * 2;
        __nv_bfloat16 h0b, l0b, h1b, l1b;
        cvt_hilo(acco[j][0] * inv0, h0b, l0b);
        cvt_hilo(acco[j][1] * inv0, h1b, l1b);
        size_t off = (size_t)rg * CDIM + col;
        *(uint32_t*)(g_attn_hi + off) = pk(h0b, h1b);
        *(uint32_t*)(g_attn_lo + off) = pk(l0b, l1b);
        cvt_hilo(acco[j][2] * inv1, h0b, l0b);
        cvt_hilo(acco[j][3] * inv1, h1b, l1b);
        off = (size_t)(rg + 8) * CDIM + col;
        *(uint32_t*)(g_attn_hi + off) = pk(h0b, h1b);
        *(uint32_t*)(g_attn_lo + off) = pk(l0b, l1b);
    }
}

// ---------------------------------------------------------------------------
// fp32 -> bf16 hi/lo elementwise convert
// ---------------------------------------------------------------------------
__global__ void __launch_bounds__(256) cvt_kernel(
    const float4* __restrict__ src, uint2* __restrict__ hi,
    uint2* __restrict__ lo, int n4)
{
    int i = blockIdx.x * blockDim.x + threadIdx.x;
    if (i >= n4) return;
    float4 v = src[i];
    __nv_bfloat16 h0, h1, h2, h3, l0, l1, l2, l3;
    cvt_hilo(v.x, h0, l0); cvt_hilo(v.y, h1, l1);
    cvt_hilo(v.z, h2, l2); cvt_hilo(v.w, h3, l3);
    hi[i] = make_uint2(pk(h0, h1), pk(h2, h3));
    lo[i] = make_uint2(pk(l0, l1), pk(l2, l3));
}

// ---------------------------------------------------------------------------
extern "C" void kernel_launch(void* const* d_in, const int* in_sizes, int n_in,
                              void* d_out, int out_size)
{
    (void)in_sizes; (void)n_in; (void)out_size;
    const float* x     = (const float*)d_in[0];
    const float* w_qkv = (const float*)d_in[1];
    const float* w_out = (const float*)d_in[2];
    const float* b_out = (const float*)d_in[3];
    float* out = (float*)d_out;

    static int attr_done = 0;
    if (!attr_done) {
        cudaFuncSetAttribute(mma_gemm, cudaFuncAttributeMaxDynamicSharedMemorySize,
                             2 * GM_BUF);
        cudaFuncSetAttribute(flash_kernel, cudaFuncAttributeMaxDynamicSharedMemorySize,
                             FL_SMEM);
        attr_done = 1;
    }

    __nv_bfloat16 *xh, *xl, *qh, *ql, *oh, *ol;
    cudaGetSymbolAddress((void**)&xh, g_x_hi);
    cudaGetSymbolAddress((void**)&xl, g_x_lo);
    cudaGetSymbolAddress((void**)&qh, g_wqkv_hi);
    cudaGetSymbolAddress((void**)&ql, g_wqkv_lo);
    cudaGetSymbolAddress((void**)&oh, g_wout_hi);
    cudaGetSymbolAddress((void**)&ol, g_wout_lo);

    {
        int n4 = MROWS * CDIM / 4;
        cvt_kernel<<<(n4 + 255) / 256, 256>>>((const float4*)x, (uint2*)xh, (uint2*)xl, n4);
        n4 = F3 * CDIM / 4;
        cvt_kernel<<<(n4 + 255) / 256, 256>>>((const float4*)w_qkv, (uint2*)qh, (uint2*)ql, n4);
        n4 = CDIM * CDIM / 4;
        cvt_kernel<<<(n4 + 255) / 256, 256>>>((const float4*)w_out, (uint2*)oh, (uint2*)ol, n4);
    }

    // 1) QKV -> g_qkv hi/lo (Q pre-scaled by 0.125)
    mma_gemm<<<dim3(F3 / 256, MROWS / 128), 256, 2 * GM_BUF>>>(0, nullptr, nullptr);
    // 2) fused flash attention -> g_attn hi/lo
    flash_kernel<<<dim3(SEQ / 128, NBH), 256, FL_SMEM>>>();
    // 3) proj -> out (+bias)
    mma_gemm<<<dim3(CDIM / 256, MROWS / 128), 256, 2 * GM_BUF>>>(2, b_out, out);
}